// round 16
// baseline (speedup 1.0000x reference)
#include <cuda_runtime.h>
#include <cstdint>

#define N_NODES 20000
#define N_EDGES 320000
#define TPW 16  // edges per warp per group

typedef unsigned long long ull;

// Scratch (device globals — no allocation allowed)
__device__ float g_sup[N_NODES * 64];    // up-projected scalars  [n][u]
__device__ float g_vup[N_NODES * 192];   // up-projected vectors  [n][u][m]
__device__ float g_msgs[N_NODES * 128];  // scalar messages       [n][u]   (m_s0 | m_s1)
__device__ float g_msgv[N_NODES * 384];  // vector messages       [n][m][p] (p<64: v0, p>=64: v1)

__device__ __forceinline__ float silu_f(float x) {
    return __fdividef(x, 1.0f + __expf(-x));
}

// ---- packed f32x2 helpers (sm_103a) ----
__device__ __forceinline__ ull pack2(float x, float y) {
    ull d; asm("mov.b64 %0, {%1, %2};" : "=l"(d) : "f"(x), "f"(y)); return d;
}
__device__ __forceinline__ void unpack2(ull v, float& x, float& y) {
    asm("mov.b64 {%0, %1}, %2;" : "=f"(x), "=f"(y) : "l"(v));
}
__device__ __forceinline__ ull fma2(ull a, ull b, ull c) {
    ull d; asm("fma.rn.f32x2 %0, %1, %2, %3;" : "=l"(d) : "l"(a), "l"(b), "l"(c)); return d;
}
// ---- paired global reduction (adjacent addresses) ----
__device__ __forceinline__ void red2(float* p, float a, float b) {
    asm volatile("red.global.add.v2.f32 [%0], {%1, %2};"
                 :: "l"(p), "f"(a), "f"(b) : "memory");
}

// ---------------------------------------------------------------------------
// Node up-projection (with fused zeroing of the message accumulators)
// ---------------------------------------------------------------------------
#define NUP_SMEM ((4096 + 4096 + 16 * 256) * 4)
#define NUP_GRID 592

__global__ __launch_bounds__(256) void nodeup_kernel(
    const float* __restrict__ nf, const float* __restrict__ W0,
    const float* __restrict__ W1) {
    extern __shared__ float smem[];
    float* sW0 = smem;            // 64x64
    float* sW1 = sW0 + 4096;      // 64x64
    float* sx  = sW1 + 4096;      // 16 x 256
    int tid = threadIdx.x;

    // --- fused zeroing of g_msgs / g_msgv ---
    {
        int idx = blockIdx.x * blockDim.x + tid;
        int stride = NUP_GRID * 256;
        const int ns = N_NODES * 128 / 4;
        const int nv = N_NODES * 384 / 4;
        float4 z = make_float4(0.f, 0.f, 0.f, 0.f);
        for (int i = idx; i < ns; i += stride) ((float4*)g_msgs)[i] = z;
        for (int i = idx; i < nv; i += stride) ((float4*)g_msgv)[i] = z;
    }

    for (int i = tid; i < 4096; i += 256) { sW0[i] = W0[i] * 0.125f; sW1[i] = W1[i] * 0.125f; }
    int ln = tid >> 4;
    int cg = tid & 15;
    const float4* w0v = (const float4*)sW0;
    const float4* w1v = (const float4*)sW1;
    const int ntiles = N_NODES / 16;
    for (int tile = blockIdx.x; tile < ntiles; tile += gridDim.x) {
        int nb = tile * 16;
        __syncthreads();
        {
            const float4* src = (const float4*)(nf + (size_t)nb * 256);
            float4* dst = (float4*)sx;
            for (int i = tid; i < 1024; i += 256) dst[i] = src[i];
        }
        __syncthreads();
        const float* x = sx + ln * 256;
        float4 aS = make_float4(0.f, 0.f, 0.f, 0.f);
        float4 a0 = aS, a1 = aS, a2 = aS;
#pragma unroll 4
        for (int u = 0; u < 64; u++) {
            float4 w0 = w0v[u * 16 + cg];
            float4 w1 = w1v[u * 16 + cg];
            float s  = x[u];
            float v0 = x[64 + 3 * u], v1 = x[64 + 3 * u + 1], v2 = x[64 + 3 * u + 2];
            aS.x += s * w0.x; aS.y += s * w0.y; aS.z += s * w0.z; aS.w += s * w0.w;
            a0.x += v0 * w1.x; a0.y += v0 * w1.y; a0.z += v0 * w1.z; a0.w += v0 * w1.w;
            a1.x += v1 * w1.x; a1.y += v1 * w1.y; a1.z += v1 * w1.z; a1.w += v1 * w1.w;
            a2.x += v2 * w1.x; a2.y += v2 * w1.y; a2.z += v2 * w1.z; a2.w += v2 * w1.w;
        }
        int n = nb + ln;
        *(float4*)(g_sup + (size_t)n * 64 + 4 * cg) = aS;
        float* vp = g_vup + (size_t)n * 192 + 12 * cg;
        ((float4*)vp)[0] = make_float4(a0.x, a1.x, a2.x, a0.y);
        ((float4*)vp)[1] = make_float4(a1.y, a2.y, a0.z, a1.z);
        ((float4*)vp)[2] = make_float4(a2.z, a0.w, a1.w, a2.w);
    }
}

// ---------------------------------------------------------------------------
// Fused edge kernel: TPW=16 per warp per weight sweep; lane owns u pair
// {2*lane, 2*lane+1}. Layer 4 runs as four quarter-passes (one output
// column-pair j each), interleaved with the two scatter halves so only two
// 16-entry accumulator arrays are live. Scatter via red.global.add.v2.f32.
// ---------------------------------------------------------------------------
#define EDGE_THREADS 512
#define EDGE_WARPS (EDGE_THREADS / 32)
#define EDGE_SMEM ((512 + 4096 + 4096 + 16384 + EDGE_WARPS * TPW * 64) * 4)

__global__ __launch_bounds__(EDGE_THREADS, 1) void edge_kernel(
    const float* __restrict__ edge_attrs, const float* __restrict__ edge_feats,
    const int* __restrict__ snd_idx, const int* __restrict__ rcv_idx,
    const float* __restrict__ M1, const float* __restrict__ M2,
    const float* __restrict__ M3, const float* __restrict__ M4) {
    extern __shared__ float smem[];
    float* sM1 = smem;
    float* sM2 = sM1 + 512;
    float* sM3 = sM2 + 4096;
    float* sM4 = sM3 + 4096;   // pre-scaled by 1/8, original layout
    float* sh  = sM4 + 16384;
    int tid = threadIdx.x;
    for (int i = tid; i < 512;  i += EDGE_THREADS) sM1[i] = M1[i];
    for (int i = tid; i < 4096; i += EDGE_THREADS) { sM2[i] = M2[i]; sM3[i] = M3[i]; }
    for (int idx = tid; idx < 16384; idx += EDGE_THREADS) sM4[idx] = M4[idx] * 0.125f;
    __syncthreads();

    int warp = tid >> 5, lane = tid & 31;
    float* hh = sh + warp * (TPW * 64);
    const int ngroups = N_EDGES / TPW;
    const float INV_SQRT3 = 0.57735026918962576f;
    const float S1 = 0.35355339059327379f;  // 1/sqrt(8)

    float2 w1r[8];
#pragma unroll
    for (int i = 0; i < 8; i++) w1r[i] = *(const float2*)&sM1[i * 64 + 2 * lane];

    for (int g = blockIdx.x * EDGE_WARPS + warp; g < ngroups; g += gridDim.x * EDGE_WARPS) {
        int e0 = g * TPW;
        // ---- layer 1 : ef(8) @ M1 -> h(64), silu ----
#pragma unroll
        for (int t = 0; t < TPW; t++) {
            const float4* p = (const float4*)(edge_feats + (size_t)(e0 + t) * 8);
            float4 A = __ldg(p), B = __ldg(p + 1);
            float a0 = A.x * w1r[0].x + A.y * w1r[1].x + A.z * w1r[2].x + A.w * w1r[3].x
                     + B.x * w1r[4].x + B.y * w1r[5].x + B.z * w1r[6].x + B.w * w1r[7].x;
            float a1 = A.x * w1r[0].y + A.y * w1r[1].y + A.z * w1r[2].y + A.w * w1r[3].y
                     + B.x * w1r[4].y + B.y * w1r[5].y + B.z * w1r[6].y + B.w * w1r[7].y;
            float2 hv;
            hv.x = silu_f(a0 * S1);
            hv.y = silu_f(a1 * S1);
            *(float2*)&hh[t * 64 + 2 * lane] = hv;
        }
        __syncwarp();

        // ---- layers 2 & 3 : column-pair packed f32x2 ----
#pragma unroll
        for (int L = 0; L < 2; L++) {
            const float* W = (L == 0) ? sM2 : sM3;
            ull acc2[TPW];
#pragma unroll
            for (int t = 0; t < TPW; t++) acc2[t] = 0ull;
            for (int i = 0; i < 64; i += 4) {
                ull wp[4];
#pragma unroll
                for (int k = 0; k < 4; k++)
                    wp[k] = *(const ull*)&W[(i + k) * 64 + 2 * lane];
#pragma unroll
                for (int t = 0; t < TPW; t++) {
                    float4 q = *(const float4*)&hh[t * 64 + i];
                    acc2[t] = fma2(pack2(q.x, q.x), wp[0], acc2[t]);
                    acc2[t] = fma2(pack2(q.y, q.y), wp[1], acc2[t]);
                    acc2[t] = fma2(pack2(q.z, q.z), wp[2], acc2[t]);
                    acc2[t] = fma2(pack2(q.w, q.w), wp[3], acc2[t]);
                }
            }
            __syncwarp();
#pragma unroll
            for (int t = 0; t < TPW; t++) {
                float x, y;
                unpack2(acc2[t], x, y);
                float2 hv;
                hv.x = silu_f(x * 0.125f);
                hv.y = silu_f(y * 0.125f);
                *(float2*)&hh[t * 64 + 2 * lane] = hv;
            }
            __syncwarp();
        }

        // ---- layer 4 + scatter : four quarter-passes (j = 0..3),
        //      scatter after j-pairs (0,1) and (2,3) ----
        ull aW[TPW];   // w_{2p}   pairs (j even)
        ull bW[TPW];   // w_{2p+1} pairs (j odd)
#pragma unroll
        for (int p = 0; p < 2; p++) {
            // quarter pass A: j = 2p
#pragma unroll
            for (int t = 0; t < TPW; t++) aW[t] = 0ull;
            for (int i = 0; i < 64; i += 4) {
                ull wp[4];
#pragma unroll
                for (int k = 0; k < 4; k++)
                    wp[k] = *(const ull*)&sM4[((i + k) << 8) + (p << 7) + 2 * lane];
#pragma unroll
                for (int t = 0; t < TPW; t++) {
                    float4 q = *(const float4*)&hh[t * 64 + i];
                    aW[t] = fma2(pack2(q.x, q.x), wp[0], aW[t]);
                    aW[t] = fma2(pack2(q.y, q.y), wp[1], aW[t]);
                    aW[t] = fma2(pack2(q.z, q.z), wp[2], aW[t]);
                    aW[t] = fma2(pack2(q.w, q.w), wp[3], aW[t]);
                }
            }
            // quarter pass B: j = 2p + 1
#pragma unroll
            for (int t = 0; t < TPW; t++) bW[t] = 0ull;
            for (int i = 0; i < 64; i += 4) {
                ull wp[4];
#pragma unroll
                for (int k = 0; k < 4; k++)
                    wp[k] = *(const ull*)&sM4[((i + k) << 8) + (p << 7) + 64 + 2 * lane];
#pragma unroll
                for (int t = 0; t < TPW; t++) {
                    float4 q = *(const float4*)&hh[t * 64 + i];
                    bW[t] = fma2(pack2(q.x, q.x), wp[0], bW[t]);
                    bW[t] = fma2(pack2(q.y, q.y), wp[1], bW[t]);
                    bW[t] = fma2(pack2(q.z, q.z), wp[2], bW[t]);
                    bW[t] = fma2(pack2(q.w, q.w), wp[3], bW[t]);
                }
            }
            // scatter this half with paired reductions
#pragma unroll
            for (int t = 0; t < TPW; t++) {
                int e = e0 + t;
                int snd = __ldg(&snd_idx[e]);
                int rcv = __ldg(&rcv_idx[e]);
                float4 ea = __ldg((const float4*)(edge_attrs + (size_t)e * 4));
                float ys = ea.x, yv0 = ea.y, yv1 = ea.z, yv2 = ea.w;
                const float* sup = g_sup + (size_t)snd * 64;
                const float* vup = g_vup + (size_t)snd * 192;
                float* ms = g_msgs + (size_t)rcv * 128;
                float* mv = g_msgv + (size_t)rcv * 384;
                int u2 = 2 * lane;
                float wAa, wAb, wBa, wBb;   // wA = w_{2p}, wB = w_{2p+1}; a/b = u2, u2+1
                unpack2(aW[t], wAa, wAb);
                unpack2(bW[t], wBa, wBb);
                if (p == 0) {
                    // w0 -> m_s0 ; w1 -> m_v0
                    float2 xs2 = __ldg((const float2*)(sup + u2));
                    red2(ms + u2, wAa * xs2.x * ys, wAb * xs2.y * ys);
                    float wxsa = wBa * xs2.x, wxsb = wBb * xs2.y;
                    red2(mv + u2,        wxsa * yv0, wxsb * yv0);
                    red2(mv + 128 + u2,  wxsa * yv1, wxsb * yv1);
                    red2(mv + 256 + u2,  wxsa * yv2, wxsb * yv2);
                } else {
                    // w2 -> m_v1 ; w3 -> m_s1
                    const float2* vp2 = (const float2*)(vup + 3 * u2);
                    float2 q0 = __ldg(vp2);       // xv0[u2], xv1[u2]
                    float2 q1 = __ldg(vp2 + 1);   // xv2[u2], xv0[u2+1]
                    float2 q2 = __ldg(vp2 + 2);   // xv1[u2+1], xv2[u2+1]
                    float dva = q0.x * yv0 + q0.y * yv1 + q1.x * yv2;
                    float dvb = q1.y * yv0 + q2.x * yv1 + q2.y * yv2;
                    red2(ms + 64 + u2, wBa * dva * INV_SQRT3, wBb * dvb * INV_SQRT3);
                    float wysa = wAa * ys, wysb = wAb * ys;
                    red2(mv + 64 + u2,   wysa * q0.x, wysb * q1.y);
                    red2(mv + 192 + u2,  wysa * q0.y, wysb * q2.x);
                    red2(mv + 320 + u2,  wysa * q1.x, wysb * q2.y);
                }
            }
        }
    }
}

// ---------------------------------------------------------------------------
// Node output: 128 threads/CTA, 16-node tiles, 2 nodes per thread.
// ---------------------------------------------------------------------------
#define NODEOUT_THREADS 128
#define NODEOUT_SMEM ((8192 + 8192 + 16 * 512) * 4)

__global__ __launch_bounds__(NODEOUT_THREADS) void nodeout_kernel(
    const float* __restrict__ WL0, const float* __restrict__ WL1,
    float* __restrict__ out) {
    extern __shared__ float smem[];
    float* sW0 = smem;            // 128x64
    float* sW1 = sW0 + 8192;      // 128x64
    float* sS  = sW1 + 8192;      // 16 x 128
    float* sV  = sS + 2048;       // 16 x 384
    int tid = threadIdx.x;
    const float SC = 0.0055242717280199021f;  // 1/(sqrt(128)*16)
    for (int i = tid; i < 8192; i += NODEOUT_THREADS) {
        sW0[i] = WL0[i] * SC; sW1[i] = WL1[i] * SC;
    }
    int ln = tid >> 4;            // 0..7 : handles nodes ln and ln+8
    int cg = tid & 15;
    const float4* w0v = (const float4*)sW0;
    const float4* w1v = (const float4*)sW1;
    const int ntiles = N_NODES / 16;
    for (int tile = blockIdx.x; tile < ntiles; tile += gridDim.x) {
        int nb = tile * 16;
        __syncthreads();
        {
            const float4* srcS = (const float4*)(g_msgs + (size_t)nb * 128);
            float4* dstS = (float4*)sS;
            for (int i = tid; i < 512; i += NODEOUT_THREADS) dstS[i] = srcS[i];
            const float4* srcV = (const float4*)(g_msgv + (size_t)nb * 384);
            float4* dstV = (float4*)sV;
            for (int i = tid; i < 1536; i += NODEOUT_THREADS) dstV[i] = srcV[i];
        }
        __syncthreads();
        const float* SA = sS + ln * 128;
        const float* SB = sS + (ln + 8) * 128;
        const float* VA = sV + ln * 384;
        const float* VB = sV + (ln + 8) * 384;
        float4 aSA = make_float4(0.f, 0.f, 0.f, 0.f);
        float4 a0A = aSA, a1A = aSA, a2A = aSA;
        float4 aSB = aSA, a0B = aSA, a1B = aSA, a2B = aSA;
        for (int u = 0; u < 128; u += 4) {
            float4 SA4  = *(const float4*)&SA[u];
            float4 VA04 = *(const float4*)&VA[u];
            float4 VA14 = *(const float4*)&VA[128 + u];
            float4 VA24 = *(const float4*)&VA[256 + u];
            float4 SB4  = *(const float4*)&SB[u];
            float4 VB04 = *(const float4*)&VB[u];
            float4 VB14 = *(const float4*)&VB[128 + u];
            float4 VB24 = *(const float4*)&VB[256 + u];
            const float sAa[4]  = {SA4.x, SA4.y, SA4.z, SA4.w};
            const float v0Aa[4] = {VA04.x, VA04.y, VA04.z, VA04.w};
            const float v1Aa[4] = {VA14.x, VA14.y, VA14.z, VA14.w};
            const float v2Aa[4] = {VA24.x, VA24.y, VA24.z, VA24.w};
            const float sBa[4]  = {SB4.x, SB4.y, SB4.z, SB4.w};
            const float v0Ba[4] = {VB04.x, VB04.y, VB04.z, VB04.w};
            const float v1Ba[4] = {VB14.x, VB14.y, VB14.z, VB14.w};
            const float v2Ba[4] = {VB24.x, VB24.y, VB24.z, VB24.w};
#pragma unroll
            for (int k = 0; k < 4; k++) {
                float4 w0 = w0v[(u + k) * 16 + cg];
                float4 w1 = w1v[(u + k) * 16 + cg];
                {
                    float s = sAa[k], v0 = v0Aa[k], v1 = v1Aa[k], v2 = v2Aa[k];
                    aSA.x += s * w0.x; aSA.y += s * w0.y; aSA.z += s * w0.z; aSA.w += s * w0.w;
                    a0A.x += v0 * w1.x; a0A.y += v0 * w1.y; a0A.z += v0 * w1.z; a0A.w += v0 * w1.w;
                    a1A.x += v1 * w1.x; a1A.y += v1 * w1.y; a1A.z += v1 * w1.z; a1A.w += v1 * w1.w;
                    a2A.x += v2 * w1.x; a2A.y += v2 * w1.y; a2A.z += v2 * w1.z; a2A.w += v2 * w1.w;
                }
                {
                    float s = sBa[k], v0 = v0Ba[k], v1 = v1Ba[k], v2 = v2Ba[k];
                    aSB.x += s * w0.x; aSB.y += s * w0.y; aSB.z += s * w0.z; aSB.w += s * w0.w;
                    a0B.x += v0 * w1.x; a0B.y += v0 * w1.y; a0B.z += v0 * w1.z; a0B.w += v0 * w1.w;
                    a1B.x += v1 * w1.x; a1B.y += v1 * w1.y; a1B.z += v1 * w1.z; a1B.w += v1 * w1.w;
                    a2B.x += v2 * w1.x; a2B.y += v2 * w1.y; a2B.z += v2 * w1.z; a2B.w += v2 * w1.w;
                }
            }
        }
#pragma unroll
        for (int h = 0; h < 2; h++) {
            int n = nb + ln + 8 * h;
            float4 aS = h ? aSB : aSA;
            float4 a0 = h ? a0B : a0A;
            float4 a1 = h ? a1B : a1A;
            float4 a2 = h ? a2B : a2A;
            float* o = out + (size_t)n * 256;
            *(float4*)(o + 4 * cg) = aS;
            float* vp = o + 64 + 12 * cg;
            ((float4*)vp)[0] = make_float4(a0.x, a1.x, a2.x, a0.y);
            ((float4*)vp)[1] = make_float4(a1.y, a2.y, a0.z, a1.z);
            ((float4*)vp)[2] = make_float4(a2.z, a0.w, a1.w, a2.w);
        }
    }
}

// ---------------------------------------------------------------------------
extern "C" void kernel_launch(void* const* d_in, const int* in_sizes, int n_in,
                              void* d_out, int out_size) {
    const float* node_feats = (const float*)d_in[1];
    const float* edge_attrs = (const float*)d_in[2];
    const float* edge_feats = (const float*)d_in[3];
    const int*   eidx       = (const int*)d_in[4];
    const float* W_up0      = (const float*)d_in[5];
    const float* W_up1      = (const float*)d_in[6];
    const float* M1         = (const float*)d_in[7];
    const float* M2         = (const float*)d_in[8];
    const float* M3         = (const float*)d_in[9];
    const float* M4         = (const float*)d_in[10];
    const float* WL0        = (const float*)d_in[11];
    const float* WL1        = (const float*)d_in[12];
    float* out = (float*)d_out;

    cudaFuncSetAttribute(edge_kernel,
                         cudaFuncAttributeMaxDynamicSharedMemorySize, EDGE_SMEM);
    cudaFuncSetAttribute(nodeout_kernel,
                         cudaFuncAttributeMaxDynamicSharedMemorySize, NODEOUT_SMEM);
    cudaFuncSetAttribute(nodeup_kernel,
                         cudaFuncAttributeMaxDynamicSharedMemorySize, NUP_SMEM);

    nodeup_kernel<<<NUP_GRID, 256, NUP_SMEM>>>(node_feats, W_up0, W_up1);
    edge_kernel<<<148, EDGE_THREADS, EDGE_SMEM>>>(edge_attrs, edge_feats,
                                                  eidx, eidx + N_EDGES,
                                                  M1, M2, M3, M4);
    nodeout_kernel<<<296, NODEOUT_THREADS, NODEOUT_SMEM>>>(WL0, WL1, out);
}

// round 17
// speedup vs baseline: 1.1001x; 1.1001x over previous
#include <cuda_runtime.h>
#include <cstdint>

#define N_NODES 20000
#define N_EDGES 320000
#define TPW 8  // edges per warp per group

typedef unsigned long long ull;

// Scratch (device globals — no allocation allowed)
__device__ float g_sup[N_NODES * 64];    // up-projected scalars  [n][u]
__device__ float g_vup[N_NODES * 192];   // up-projected vectors  [n][u][m]
__device__ float g_msgs[N_NODES * 128];  // scalar messages       [n][u]   (m_s0 | m_s1)
__device__ float g_msgv[N_NODES * 384];  // vector messages       [n][m][p] (p<64: v0, p>=64: v1)

__device__ __forceinline__ float silu_f(float x) {
    return __fdividef(x, 1.0f + __expf(-x));
}

// ---- packed f32x2 helpers (sm_103a) ----
__device__ __forceinline__ ull pack2(float x, float y) {
    ull d; asm("mov.b64 %0, {%1, %2};" : "=l"(d) : "f"(x), "f"(y)); return d;
}
__device__ __forceinline__ void unpack2(ull v, float& x, float& y) {
    asm("mov.b64 {%0, %1}, %2;" : "=f"(x), "=f"(y) : "l"(v));
}
__device__ __forceinline__ ull fma2(ull a, ull b, ull c) {
    ull d; asm("fma.rn.f32x2 %0, %1, %2, %3;" : "=l"(d) : "l"(a), "l"(b), "l"(c)); return d;
}
// ---- paired global reduction (adjacent addresses) ----
__device__ __forceinline__ void red2(float* p, float a, float b) {
    asm volatile("red.global.add.v2.f32 [%0], {%1, %2};"
                 :: "l"(p), "f"(a), "f"(b) : "memory");
}

// ---------------------------------------------------------------------------
// Node up-projection (with fused zeroing of the message accumulators)
// ---------------------------------------------------------------------------
#define NUP_SMEM ((4096 + 4096 + 16 * 256) * 4)
#define NUP_GRID 592

__global__ __launch_bounds__(256) void nodeup_kernel(
    const float* __restrict__ nf, const float* __restrict__ W0,
    const float* __restrict__ W1) {
    extern __shared__ float smem[];
    float* sW0 = smem;            // 64x64
    float* sW1 = sW0 + 4096;      // 64x64
    float* sx  = sW1 + 4096;      // 16 x 256
    int tid = threadIdx.x;

    // --- fused zeroing of g_msgs / g_msgv ---
    {
        int idx = blockIdx.x * blockDim.x + tid;
        int stride = NUP_GRID * 256;
        const int ns = N_NODES * 128 / 4;
        const int nv = N_NODES * 384 / 4;
        float4 z = make_float4(0.f, 0.f, 0.f, 0.f);
        for (int i = idx; i < ns; i += stride) ((float4*)g_msgs)[i] = z;
        for (int i = idx; i < nv; i += stride) ((float4*)g_msgv)[i] = z;
    }

    for (int i = tid; i < 4096; i += 256) { sW0[i] = W0[i] * 0.125f; sW1[i] = W1[i] * 0.125f; }
    int ln = tid >> 4;
    int cg = tid & 15;
    const float4* w0v = (const float4*)sW0;
    const float4* w1v = (const float4*)sW1;
    const int ntiles = N_NODES / 16;
    for (int tile = blockIdx.x; tile < ntiles; tile += gridDim.x) {
        int nb = tile * 16;
        __syncthreads();
        {
            const float4* src = (const float4*)(nf + (size_t)nb * 256);
            float4* dst = (float4*)sx;
            for (int i = tid; i < 1024; i += 256) dst[i] = src[i];
        }
        __syncthreads();
        const float* x = sx + ln * 256;
        float4 aS = make_float4(0.f, 0.f, 0.f, 0.f);
        float4 a0 = aS, a1 = aS, a2 = aS;
#pragma unroll 4
        for (int u = 0; u < 64; u++) {
            float4 w0 = w0v[u * 16 + cg];
            float4 w1 = w1v[u * 16 + cg];
            float s  = x[u];
            float v0 = x[64 + 3 * u], v1 = x[64 + 3 * u + 1], v2 = x[64 + 3 * u + 2];
            aS.x += s * w0.x; aS.y += s * w0.y; aS.z += s * w0.z; aS.w += s * w0.w;
            a0.x += v0 * w1.x; a0.y += v0 * w1.y; a0.z += v0 * w1.z; a0.w += v0 * w1.w;
            a1.x += v1 * w1.x; a1.y += v1 * w1.y; a1.z += v1 * w1.z; a1.w += v1 * w1.w;
            a2.x += v2 * w1.x; a2.y += v2 * w1.y; a2.z += v2 * w1.z; a2.w += v2 * w1.w;
        }
        int n = nb + ln;
        *(float4*)(g_sup + (size_t)n * 64 + 4 * cg) = aS;
        float* vp = g_vup + (size_t)n * 192 + 12 * cg;
        ((float4*)vp)[0] = make_float4(a0.x, a1.x, a2.x, a0.y);
        ((float4*)vp)[1] = make_float4(a1.y, a2.y, a0.z, a1.z);
        ((float4*)vp)[2] = make_float4(a2.z, a0.w, a1.w, a2.w);
    }
}

// ---------------------------------------------------------------------------
// Fused edge kernel: lane owns u = {2*lane, 2*lane+1} throughout.
// Layer 4 weight pairs are natural adjacent M4 entries (no permute).
// Scatter uses red.global.add.v2.f32 on adjacent addresses (8 per lane-edge).
// ---------------------------------------------------------------------------
#define EDGE_THREADS 512
#define EDGE_WARPS (EDGE_THREADS / 32)
#define EDGE_SMEM ((512 + 4096 + 4096 + 16384 + EDGE_WARPS * TPW * 64) * 4)

__global__ __launch_bounds__(EDGE_THREADS, 1) void edge_kernel(
    const float* __restrict__ edge_attrs, const float* __restrict__ edge_feats,
    const int* __restrict__ snd_idx, const int* __restrict__ rcv_idx,
    const float* __restrict__ M1, const float* __restrict__ M2,
    const float* __restrict__ M3, const float* __restrict__ M4) {
    extern __shared__ float smem[];
    float* sM1 = smem;
    float* sM2 = sM1 + 512;
    float* sM3 = sM2 + 4096;
    float* sM4 = sM3 + 4096;   // pre-scaled by 1/8, original layout
    float* sh  = sM4 + 16384;
    int tid = threadIdx.x;
    for (int i = tid; i < 512;  i += EDGE_THREADS) sM1[i] = M1[i];
    for (int i = tid; i < 4096; i += EDGE_THREADS) { sM2[i] = M2[i]; sM3[i] = M3[i]; }
    for (int idx = tid; idx < 16384; idx += EDGE_THREADS) sM4[idx] = M4[idx] * 0.125f;
    __syncthreads();

    int warp = tid >> 5, lane = tid & 31;
    float* hh = sh + warp * (TPW * 64);
    const int ngroups = N_EDGES / TPW;
    const float INV_SQRT3 = 0.57735026918962576f;
    const float S1 = 0.35355339059327379f;  // 1/sqrt(8)

    float2 w1r[8];
#pragma unroll
    for (int i = 0; i < 8; i++) w1r[i] = *(const float2*)&sM1[i * 64 + 2 * lane];

    for (int g = blockIdx.x * EDGE_WARPS + warp; g < ngroups; g += gridDim.x * EDGE_WARPS) {
        int e0 = g * TPW;
        // ---- layer 1 : ef(8) @ M1 -> h(64), silu ----
#pragma unroll
        for (int t = 0; t < TPW; t++) {
            const float4* p = (const float4*)(edge_feats + (size_t)(e0 + t) * 8);
            float4 A = __ldg(p), B = __ldg(p + 1);
            float a0 = A.x * w1r[0].x + A.y * w1r[1].x + A.z * w1r[2].x + A.w * w1r[3].x
                     + B.x * w1r[4].x + B.y * w1r[5].x + B.z * w1r[6].x + B.w * w1r[7].x;
            float a1 = A.x * w1r[0].y + A.y * w1r[1].y + A.z * w1r[2].y + A.w * w1r[3].y
                     + B.x * w1r[4].y + B.y * w1r[5].y + B.z * w1r[6].y + B.w * w1r[7].y;
            float2 hv;
            hv.x = silu_f(a0 * S1);
            hv.y = silu_f(a1 * S1);
            *(float2*)&hh[t * 64 + 2 * lane] = hv;
        }
        __syncwarp();

        // ---- layers 2 & 3 : column-pair packed f32x2 ----
#pragma unroll
        for (int L = 0; L < 2; L++) {
            const float* W = (L == 0) ? sM2 : sM3;
            ull acc2[TPW];
#pragma unroll
            for (int t = 0; t < TPW; t++) acc2[t] = 0ull;
            for (int i = 0; i < 64; i += 4) {
                ull wp[4];
#pragma unroll
                for (int k = 0; k < 4; k++)
                    wp[k] = *(const ull*)&W[(i + k) * 64 + 2 * lane];
#pragma unroll
                for (int t = 0; t < TPW; t++) {
                    float4 q = *(const float4*)&hh[t * 64 + i];
                    acc2[t] = fma2(pack2(q.x, q.x), wp[0], acc2[t]);
                    acc2[t] = fma2(pack2(q.y, q.y), wp[1], acc2[t]);
                    acc2[t] = fma2(pack2(q.z, q.z), wp[2], acc2[t]);
                    acc2[t] = fma2(pack2(q.w, q.w), wp[3], acc2[t]);
                }
            }
            __syncwarp();
#pragma unroll
            for (int t = 0; t < TPW; t++) {
                float x, y;
                unpack2(acc2[t], x, y);
                float2 hv;
                hv.x = silu_f(x * 0.125f);
                hv.y = silu_f(y * 0.125f);
                *(float2*)&hh[t * 64 + 2 * lane] = hv;
            }
            __syncwarp();
        }

        // ---- layer 4 + scatter : two half-passes over (w_{2p}, w_{2p+1}),
        //      lane computing columns 2*lane, 2*lane+1 of each ----
#pragma unroll
        for (int p = 0; p < 2; p++) {
            ull a4[TPW][2];   // [0]: w_{2p} pair, [1]: w_{2p+1} pair
#pragma unroll
            for (int t = 0; t < TPW; t++) { a4[t][0] = 0ull; a4[t][1] = 0ull; }
            for (int i = 0; i < 64; i += 4) {
                float ha[TPW][4];
#pragma unroll
                for (int t = 0; t < TPW; t++)
                    *(float4*)ha[t] = *(const float4*)&hh[t * 64 + i];
#pragma unroll
                for (int k = 0; k < 4; k++) {
                    const float* wr = &sM4[((i + k) << 8) + (p << 7) + 2 * lane];
                    ull wpa = *(const ull*)(wr);        // w_{2p}[2l], w_{2p}[2l+1]
                    ull wpb = *(const ull*)(wr + 64);   // w_{2p+1} pair
#pragma unroll
                    for (int t = 0; t < TPW; t++) {
                        ull aa = pack2(ha[t][k], ha[t][k]);
                        a4[t][0] = fma2(aa, wpa, a4[t][0]);
                        a4[t][1] = fma2(aa, wpb, a4[t][1]);
                    }
                }
            }
            // scatter this half with paired reductions
#pragma unroll
            for (int t = 0; t < TPW; t++) {
                int e = e0 + t;
                int snd = __ldg(&snd_idx[e]);
                int rcv = __ldg(&rcv_idx[e]);
                float4 ea = __ldg((const float4*)(edge_attrs + (size_t)e * 4));
                float ys = ea.x, yv0 = ea.y, yv1 = ea.z, yv2 = ea.w;
                const float* sup = g_sup + (size_t)snd * 64;
                const float* vup = g_vup + (size_t)snd * 192;
                float* ms = g_msgs + (size_t)rcv * 128;
                float* mv = g_msgv + (size_t)rcv * 384;
                int u2 = 2 * lane;
                float wAa, wAb, wBa, wBb;   // wA = w_{2p}, wB = w_{2p+1}; a/b = u2, u2+1
                unpack2(a4[t][0], wAa, wAb);
                unpack2(a4[t][1], wBa, wBb);
                if (p == 0) {
                    // w0 -> m_s0 ; w1 -> m_v0
                    float2 xs2 = __ldg((const float2*)(sup + u2));
                    red2(ms + u2, wAa * xs2.x * ys, wAb * xs2.y * ys);
                    float wxsa = wBa * xs2.x, wxsb = wBb * xs2.y;
                    red2(mv + u2,        wxsa * yv0, wxsb * yv0);
                    red2(mv + 128 + u2,  wxsa * yv1, wxsb * yv1);
                    red2(mv + 256 + u2,  wxsa * yv2, wxsb * yv2);
                } else {
                    // w2 -> m_v1 ; w3 -> m_s1
                    const float2* vp2 = (const float2*)(vup + 3 * u2);
                    float2 q0 = __ldg(vp2);       // xv0[u2], xv1[u2]
                    float2 q1 = __ldg(vp2 + 1);   // xv2[u2], xv0[u2+1]
                    float2 q2 = __ldg(vp2 + 2);   // xv1[u2+1], xv2[u2+1]
                    float dva = q0.x * yv0 + q0.y * yv1 + q1.x * yv2;
                    float dvb = q1.y * yv0 + q2.x * yv1 + q2.y * yv2;
                    red2(ms + 64 + u2, wBa * dva * INV_SQRT3, wBb * dvb * INV_SQRT3);
                    float wysa = wAa * ys, wysb = wAb * ys;
                    red2(mv + 64 + u2,   wysa * q0.x, wysb * q1.y);
                    red2(mv + 192 + u2,  wysa * q0.y, wysb * q2.x);
                    red2(mv + 320 + u2,  wysa * q1.x, wysb * q2.y);
                }
            }
        }
    }
}

// ---------------------------------------------------------------------------
// Node output: 128 threads/CTA, 16-node tiles, 2 nodes per thread.
// ---------------------------------------------------------------------------
#define NODEOUT_THREADS 128
#define NODEOUT_SMEM ((8192 + 8192 + 16 * 512) * 4)

__global__ __launch_bounds__(NODEOUT_THREADS) void nodeout_kernel(
    const float* __restrict__ WL0, const float* __restrict__ WL1,
    float* __restrict__ out) {
    extern __shared__ float smem[];
    float* sW0 = smem;            // 128x64
    float* sW1 = sW0 + 8192;      // 128x64
    float* sS  = sW1 + 8192;      // 16 x 128
    float* sV  = sS + 2048;       // 16 x 384
    int tid = threadIdx.x;
    const float SC = 0.0055242717280199021f;  // 1/(sqrt(128)*16)
    for (int i = tid; i < 8192; i += NODEOUT_THREADS) {
        sW0[i] = WL0[i] * SC; sW1[i] = WL1[i] * SC;
    }
    int ln = tid >> 4;            // 0..7 : handles nodes ln and ln+8
    int cg = tid & 15;
    const float4* w0v = (const float4*)sW0;
    const float4* w1v = (const float4*)sW1;
    const int ntiles = N_NODES / 16;
    for (int tile = blockIdx.x; tile < ntiles; tile += gridDim.x) {
        int nb = tile * 16;
        __syncthreads();
        {
            const float4* srcS = (const float4*)(g_msgs + (size_t)nb * 128);
            float4* dstS = (float4*)sS;
            for (int i = tid; i < 512; i += NODEOUT_THREADS) dstS[i] = srcS[i];
            const float4* srcV = (const float4*)(g_msgv + (size_t)nb * 384);
            float4* dstV = (float4*)sV;
            for (int i = tid; i < 1536; i += NODEOUT_THREADS) dstV[i] = srcV[i];
        }
        __syncthreads();
        const float* SA = sS + ln * 128;
        const float* SB = sS + (ln + 8) * 128;
        const float* VA = sV + ln * 384;
        const float* VB = sV + (ln + 8) * 384;
        float4 aSA = make_float4(0.f, 0.f, 0.f, 0.f);
        float4 a0A = aSA, a1A = aSA, a2A = aSA;
        float4 aSB = aSA, a0B = aSA, a1B = aSA, a2B = aSA;
        for (int u = 0; u < 128; u += 4) {
            float4 SA4  = *(const float4*)&SA[u];
            float4 VA04 = *(const float4*)&VA[u];
            float4 VA14 = *(const float4*)&VA[128 + u];
            float4 VA24 = *(const float4*)&VA[256 + u];
            float4 SB4  = *(const float4*)&SB[u];
            float4 VB04 = *(const float4*)&VB[u];
            float4 VB14 = *(const float4*)&VB[128 + u];
            float4 VB24 = *(const float4*)&VB[256 + u];
            const float sAa[4]  = {SA4.x, SA4.y, SA4.z, SA4.w};
            const float v0Aa[4] = {VA04.x, VA04.y, VA04.z, VA04.w};
            const float v1Aa[4] = {VA14.x, VA14.y, VA14.z, VA14.w};
            const float v2Aa[4] = {VA24.x, VA24.y, VA24.z, VA24.w};
            const float sBa[4]  = {SB4.x, SB4.y, SB4.z, SB4.w};
            const float v0Ba[4] = {VB04.x, VB04.y, VB04.z, VB04.w};
            const float v1Ba[4] = {VB14.x, VB14.y, VB14.z, VB14.w};
            const float v2Ba[4] = {VB24.x, VB24.y, VB24.z, VB24.w};
#pragma unroll
            for (int k = 0; k < 4; k++) {
                float4 w0 = w0v[(u + k) * 16 + cg];
                float4 w1 = w1v[(u + k) * 16 + cg];
                {
                    float s = sAa[k], v0 = v0Aa[k], v1 = v1Aa[k], v2 = v2Aa[k];
                    aSA.x += s * w0.x; aSA.y += s * w0.y; aSA.z += s * w0.z; aSA.w += s * w0.w;
                    a0A.x += v0 * w1.x; a0A.y += v0 * w1.y; a0A.z += v0 * w1.z; a0A.w += v0 * w1.w;
                    a1A.x += v1 * w1.x; a1A.y += v1 * w1.y; a1A.z += v1 * w1.z; a1A.w += v1 * w1.w;
                    a2A.x += v2 * w1.x; a2A.y += v2 * w1.y; a2A.z += v2 * w1.z; a2A.w += v2 * w1.w;
                }
                {
                    float s = sBa[k], v0 = v0Ba[k], v1 = v1Ba[k], v2 = v2Ba[k];
                    aSB.x += s * w0.x; aSB.y += s * w0.y; aSB.z += s * w0.z; aSB.w += s * w0.w;
                    a0B.x += v0 * w1.x; a0B.y += v0 * w1.y; a0B.z += v0 * w1.z; a0B.w += v0 * w1.w;
                    a1B.x += v1 * w1.x; a1B.y += v1 * w1.y; a1B.z += v1 * w1.z; a1B.w += v1 * w1.w;
                    a2B.x += v2 * w1.x; a2B.y += v2 * w1.y; a2B.z += v2 * w1.z; a2B.w += v2 * w1.w;
                }
            }
        }
#pragma unroll
        for (int h = 0; h < 2; h++) {
            int n = nb + ln + 8 * h;
            float4 aS = h ? aSB : aSA;
            float4 a0 = h ? a0B : a0A;
            float4 a1 = h ? a1B : a1A;
            float4 a2 = h ? a2B : a2A;
            float* o = out + (size_t)n * 256;
            *(float4*)(o + 4 * cg) = aS;
            float* vp = o + 64 + 12 * cg;
            ((float4*)vp)[0] = make_float4(a0.x, a1.x, a2.x, a0.y);
            ((float4*)vp)[1] = make_float4(a1.y, a2.y, a0.z, a1.z);
            ((float4*)vp)[2] = make_float4(a2.z, a0.w, a1.w, a2.w);
        }
    }
}

// ---------------------------------------------------------------------------
extern "C" void kernel_launch(void* const* d_in, const int* in_sizes, int n_in,
                              void* d_out, int out_size) {
    const float* node_feats = (const float*)d_in[1];
    const float* edge_attrs = (const float*)d_in[2];
    const float* edge_feats = (const float*)d_in[3];
    const int*   eidx       = (const int*)d_in[4];
    const float* W_up0      = (const float*)d_in[5];
    const float* W_up1      = (const float*)d_in[6];
    const float* M1         = (const float*)d_in[7];
    const float* M2         = (const float*)d_in[8];
    const float* M3         = (const float*)d_in[9];
    const float* M4         = (const float*)d_in[10];
    const float* WL0        = (const float*)d_in[11];
    const float* WL1        = (const float*)d_in[12];
    float* out = (float*)d_out;

    cudaFuncSetAttribute(edge_kernel,
                         cudaFuncAttributeMaxDynamicSharedMemorySize, EDGE_SMEM);
    cudaFuncSetAttribute(nodeout_kernel,
                         cudaFuncAttributeMaxDynamicSharedMemorySize, NODEOUT_SMEM);
    cudaFuncSetAttribute(nodeup_kernel,
                         cudaFuncAttributeMaxDynamicSharedMemorySize, NUP_SMEM);

    nodeup_kernel<<<NUP_GRID, 256, NUP_SMEM>>>(node_feats, W_up0, W_up1);
    edge_kernel<<<148, EDGE_THREADS, EDGE_SMEM>>>(edge_attrs, edge_feats,
                                                  eidx, eidx + N_EDGES,
                                                  M1, M2, M3, M4);
    nodeout_kernel<<<296, NODEOUT_THREADS, NODEOUT_SMEM>>>(WL0, WL1, out);
}